// round 10
// baseline (speedup 1.0000x reference)
#include <cuda_runtime.h>
#include <cuda_fp16.h>
#include <cstdint>

// GridEncoder (instant-ngp style), D=3, L=16, C=2, H=16, PLS=2, log2_hashmap=19,
// align_corners=false.
//
// R8: lane-paired gathers. Warp = 1 point x 16 levels x 2 lanes.
//   Even lane loads the four x0-corners, odd lane the four x1-corners, in 4
//   warp-wide LDG.32s. Pair indices differ by (2^m - 1) -> same 128B line
//   ~97% of the time -> L1tex coalesces the pair into ONE wavefront.
//   Dense levels: lane pair splits the 32B cell record (2xLDG.128, 1 line).
//   Partials combined with one shfl_xor; STG.32 fully coalesced.

#define PRIME1 2654435761u
#define PRIME2 805459861u
#define HASH_MASK 0x7FFFFu
#define TOTAL_PARAMS 7131240
#define NCELLS 299008            // 16^3 + 32^3 + 64^3

__device__ __align__(16) __half2 g_embh[TOTAL_PARAMS];   // 28.5 MB half2 table
__device__ __align__(32) uint4   g_celld[2 * NCELLS];    // 9.6 MB dense cell table

__constant__ uint32_t c_off[16] = {
    0u, 4920u, 40864u, 315496u,
    839784u, 1364072u, 1888360u, 2412648u,
    2936936u, 3461224u, 3985512u, 4509800u,
    5034088u, 5558376u, 6082664u, 6606952u
};
__constant__ float c_scale[16] = {
    15.f, 31.f, 63.f, 127.f, 255.f, 511.f, 1023.f, 2047.f,
    4095.f, 8191.f, 16383.f, 32767.f, 65535.f, 131071.f, 262143.f, 524287.f
};
__constant__ uint32_t c_celloff[3] = {0u, 4096u, 36864u};

// fp32 [N,2] -> half2 [N]; 4 entries per thread, one 16B store.
__global__ void __launch_bounds__(256)
convert_kernel(const float4* __restrict__ emb, int nquads)
{
    int i = blockIdx.x * blockDim.x + threadIdx.x;
    if (i < nquads) {
        float4 v0 = __ldg(&emb[2 * i + 0]);
        float4 v1 = __ldg(&emb[2 * i + 1]);
        uint4 q;
        __half2 h0 = __floats2half2_rn(v0.x, v0.y);
        __half2 h1 = __floats2half2_rn(v0.z, v0.w);
        __half2 h2 = __floats2half2_rn(v1.x, v1.y);
        __half2 h3 = __floats2half2_rn(v1.z, v1.w);
        q.x = *reinterpret_cast<uint32_t*>(&h0);
        q.y = *reinterpret_cast<uint32_t*>(&h1);
        q.z = *reinterpret_cast<uint32_t*>(&h2);
        q.w = *reinterpret_cast<uint32_t*>(&h3);
        reinterpret_cast<uint4*>(g_embh)[i] = q;
    }
}

// Build the dense cell table: record c = { z0 plane: (x0y0,x1y0,x0y1,x1y1),
//                                          z1 plane: same }
__global__ void __launch_bounds__(256)
cell_kernel(int ncells)
{
    int i = blockIdx.x * blockDim.x + threadIdx.x;
    if (i >= ncells) return;

    uint32_t lc, sft, base, off;
    if (i < 4096)        { lc = i;          sft = 4u; base = 17u; off = 0u; }
    else if (i < 36864)  { lc = i - 4096;   sft = 5u; base = 33u; off = 4920u; }
    else                 { lc = i - 36864;  sft = 6u; base = 65u; off = 40864u; }

    uint32_t mask = (1u << sft) - 1u;
    uint32_t gx = lc & mask;
    uint32_t gy = (lc >> sft) & mask;
    uint32_t gz = lc >> (2u * sft);

    uint32_t b2 = base * base;
    uint32_t s = off + gx + gy * base + gz * b2;

    const uint32_t* e = reinterpret_cast<const uint32_t*>(g_embh);
    uint4 qa, qb;
    qa.x = e[s];             qa.y = e[s + 1u];
    qa.z = e[s + base];      qa.w = e[s + base + 1u];
    qb.x = e[s + b2];        qb.y = e[s + b2 + 1u];
    qb.z = e[s + base + b2]; qb.w = e[s + base + b2 + 1u];

    g_celld[2 * i + 0] = qa;
    g_celld[2 * i + 1] = qb;
}

__device__ __forceinline__ float2 h2f(uint32_t h)
{
    __half2 v = *reinterpret_cast<__half2*>(&h);
    return __half22float2(v);
}

__global__ void __launch_bounds__(256)
grid_encode_kernel(const float* __restrict__ in,
                   float* __restrict__ out,
                   int B)
{
    int t = blockIdx.x * blockDim.x + threadIdx.x;
    int p = t >> 5;                 // warp covers one point
    int w = t & 31;
    int l = w >> 1;                 // level
    uint32_t c = (uint32_t)(w & 1); // corner side (x side / z plane / channel)
    if (p >= B) return;

    // map inputs from [-1,1] to [0,1] (broadcast loads, 1 line per warp each)
    float x = (in[p * 3 + 0] + 1.0f) * 0.5f;
    float y = (in[p * 3 + 1] + 1.0f) * 0.5f;
    float z = (in[p * 3 + 2] + 1.0f) * 0.5f;

    float scale = c_scale[l];
    float px = fmaf(x, scale, 0.5f);
    float py = fmaf(y, scale, 0.5f);
    float pz = fmaf(z, scale, 0.5f);

    float fx = floorf(px), fy = floorf(py), fz = floorf(pz);
    uint32_t gx = (uint32_t)fx, gy = (uint32_t)fy, gz = (uint32_t)fz;
    float rx = px - fx, ry = py - fy, rz = pz - fz;

    float wx0 = 1.0f - rx, wy0 = 1.0f - ry, wz0 = 1.0f - rz;

    float a0p, a1p;   // this lane's partial for channels 0 and 1

    if (l >= 3) {
        // hash path: this lane owns x-side c; 4 scattered LDG.32 where lane
        // pairs share a 128B line ~97% of the time.
        uint32_t off = c_off[l];
        uint32_t xc = gx + c;
        uint32_t y0 = gy * PRIME1, y1 = y0 + PRIME1;
        uint32_t z0 = gz * PRIME2, z1 = z0 + PRIME2;
        uint32_t i0 = ((xc ^ y0 ^ z0) & HASH_MASK) + off;   // (y0,z0)
        uint32_t i1 = ((xc ^ y1 ^ z0) & HASH_MASK) + off;   // (y1,z0)
        uint32_t i2 = ((xc ^ y0 ^ z1) & HASH_MASK) + off;   // (y0,z1)
        uint32_t i3 = ((xc ^ y1 ^ z1) & HASH_MASK) + off;   // (y1,z1)

        const uint32_t* e = reinterpret_cast<const uint32_t*>(g_embh);
        uint32_t h0 = __ldg(e + i0);
        uint32_t h1 = __ldg(e + i1);
        uint32_t h2 = __ldg(e + i2);
        uint32_t h3 = __ldg(e + i3);

        float2 e0 = h2f(h0), e1 = h2f(h1), e2 = h2f(h2), e3 = h2f(h3);

        float wxc = c ? rx : wx0;
        float pw0 = wy0 * wz0, pw1 = ry * wz0, pw2 = wy0 * rz, pw3 = ry * rz;

        float s0 = pw0 * e0.x;       float s1 = pw0 * e0.y;
        s0 = fmaf(pw1, e1.x, s0);    s1 = fmaf(pw1, e1.y, s1);
        s0 = fmaf(pw2, e2.x, s0);    s1 = fmaf(pw2, e2.y, s1);
        s0 = fmaf(pw3, e3.x, s0);    s1 = fmaf(pw3, e3.y, s1);
        a0p = wxc * s0;
        a1p = wxc * s1;
    } else {
        // dense path: lane pair splits the 32B cell record; one line total.
        uint32_t sft = 4u + (uint32_t)l;
        uint32_t cell = c_celloff[l] + gx + (gy << sft) + (gz << (sft + sft));
        uint4 q = __ldg(&g_celld[2u * cell + c]);   // z-plane c

        float2 e0 = h2f(q.x);   // (x0,y0)
        float2 e1 = h2f(q.y);   // (x1,y0)
        float2 e2 = h2f(q.z);   // (x0,y1)
        float2 e3 = h2f(q.w);   // (x1,y1)

        float wzc = c ? rz : wz0;
        float u0 = wx0 * wy0, u1 = rx * wy0, u2 = wx0 * ry, u3 = rx * ry;

        float s0 = u0 * e0.x;        float s1 = u0 * e0.y;
        s0 = fmaf(u1, e1.x, s0);     s1 = fmaf(u1, e1.y, s1);
        s0 = fmaf(u2, e2.x, s0);     s1 = fmaf(u2, e2.y, s1);
        s0 = fmaf(u3, e3.x, s0);     s1 = fmaf(u3, e3.y, s1);
        a0p = wzc * s0;
        a1p = wzc * s1;
    }

    // Pair-combine: lane c ends up with channel c's full value.
    float send = c ? a0p : a1p;
    float recv = __shfl_xor_sync(0xFFFFFFFFu, send, 1);
    float full = (c ? a1p : a0p) + recv;

    // out[p][2l + c]; lane index w = 2l + c -> coalesced 128B per warp
    out[p * 32 + w] = full;
}

extern "C" void kernel_launch(void* const* d_in, const int* in_sizes, int n_in,
                              void* d_out, int out_size) {
    const float*  inputs = (const float*)d_in[0];       // [B, 3]
    const float4* emb4   = (const float4*)d_in[1];      // fp32 table viewed as float4
    float*        out    = (float*)d_out;               // [B, 32] floats

    int B = in_sizes[0] / 3;

    // 1) fp32 -> half2 table (TOTAL_PARAMS divisible by 4)
    int nquads = TOTAL_PARAMS / 4;
    convert_kernel<<<(nquads + 255) / 256, 256>>>(emb4, nquads);

    // 2) dense cell table (same stream -> ordered after convert)
    cell_kernel<<<(NCELLS + 255) / 256, 256>>>(NCELLS);

    // 3) main encode: one warp per point (16 levels x 2 lanes)
    int threads = 256;
    long long total = (long long)B * 32;
    int blocks = (int)((total + threads - 1) / threads);
    grid_encode_kernel<<<blocks, threads>>>(inputs, out, B);
}